// round 3
// baseline (speedup 1.0000x reference)
#include <cuda_runtime.h>
#include <cuda_bf16.h>

// SST: sst[b, k(b,f,t), t] += coeffs[b,f,t], k = clip(f + adj, 0, F-1),
// adj = signbit(x[t+1]) - signbit(x[t]) in {-1,0,+1} (adj=0 at t=T-1).
// k in {f-1, f, f+1} -> scatter re-expressed as rolling gather along F with
// three register accumulators (rows f-1, f, f+1).
//
// R3: fully peeled structure. The interior 30-iteration loop is branch-free
// (no f-bounds check, no store predicate, no edge clamps); ghost rows and the
// F-edge clamp rows (f==0, f==Fdim-1) are handled in peeled prologue/epilogue.
// __launch_bounds__(128,14) pins regs <= ~36 so the grid's ~13.9 CTAs/SM fit.

constexpr int Bdim = 16;
constexpr int Fdim = 256;
constexpr int Tdim = 8192;
constexpr int TPB  = 128;
constexpr int NSEG = 8;
constexpr int SEG  = Fdim / NSEG;   // 32

__device__ __forceinline__ int sgnbit(float x) {
    return (int)(__float_as_uint(x) >> 31);   // matches angle(): pi iff sign bit
}

// Load one row strip and compute per-element frequency shifts d in {-1,0,+1}.
__device__ __forceinline__ void row_d(const float* __restrict__ row, int lane,
                                      bool notlast, float4& v,
                                      int& d0, int& d1, int& d2, int& d3) {
    v = *reinterpret_cast<const float4*>(row);
    const int s0 = sgnbit(v.x);
    const int s1 = sgnbit(v.y);
    const int s2 = sgnbit(v.z);
    const int s3 = sgnbit(v.w);
    // sign of element t0+4 = next lane's s0; lane 31 crosses the warp boundary
    // and takes a (predicated, L1-resident) scalar load instead.
    int s4 = __shfl_down_sync(0xffffffffu, s0, 1);
    if (lane == 31) s4 = notlast ? sgnbit(__ldg(row + 4)) : s3;
    d0 = s1 - s0;
    d1 = s2 - s1;
    d2 = s3 - s2;
    d3 = notlast ? (s4 - s3) : 0;   // pad: adj=0 at t=T-1
}

#define ACCUM3(A, B, C, v, d0, d1, d2, d3)                                     \
    do {                                                                       \
        A.x += (d0 < 0) ? v.x : 0.f;                                           \
        B.x += (d0 == 0) ? v.x : 0.f;                                          \
        C.x += (d0 > 0) ? v.x : 0.f;                                           \
        A.y += (d1 < 0) ? v.y : 0.f;                                           \
        B.y += (d1 == 0) ? v.y : 0.f;                                          \
        C.y += (d1 > 0) ? v.y : 0.f;                                           \
        A.z += (d2 < 0) ? v.z : 0.f;                                           \
        B.z += (d2 == 0) ? v.z : 0.f;                                          \
        C.z += (d2 > 0) ? v.z : 0.f;                                           \
        A.w += (d3 < 0) ? v.w : 0.f;                                           \
        B.w += (d3 == 0) ? v.w : 0.f;                                          \
        C.w += (d3 > 0) ? v.w : 0.f;                                           \
    } while (0)

__global__ __launch_bounds__(TPB, 14)
void sst_gather_kernel(const float* __restrict__ in, float* __restrict__ out) {
    const int t0   = (blockIdx.x * TPB + threadIdx.x) * 4;
    const int b    = blockIdx.y;
    const int fs   = blockIdx.z * SEG;         // first output row of this block
    const int lane = threadIdx.x & 31;
    const bool notlast = (t0 + 4) < Tdim;

    const size_t bofs = (size_t)b * Fdim * Tdim;
    const float* __restrict__ ibase = in  + bofs + t0;
    float*       __restrict__ obase = out + bofs + t0;

    const float4 z = make_float4(0.f, 0.f, 0.f, 0.f);
    float4 A, B = z, C = z;
    float4 v;
    int d0, d1, d2, d3;

    // ---- lower ghost row fs-1: contributes only to out[fs] (d>0 part) ----
    if (fs > 0) {   // block-uniform
        row_d(ibase + (size_t)(fs - 1) * Tdim, lane, notlast, v, d0, d1, d2, d3);
        B.x += (d0 > 0) ? v.x : 0.f;
        B.y += (d1 > 0) ? v.y : 0.f;
        B.z += (d2 > 0) ? v.z : 0.f;
        B.w += (d3 > 0) ? v.w : 0.f;
    }

    // ---- first interior row f = fs (holds the f==0 clamp; no store yet) ----
    row_d(ibase + (size_t)fs * Tdim, lane, notlast, v, d0, d1, d2, d3);
    if (fs == 0) {   // clip at lower F edge: down-moves stay in row 0
        d0 = max(d0, 0); d1 = max(d1, 0); d2 = max(d2, 0); d3 = max(d3, 0);
    }
    // A-part (d<0 -> out[fs-1]) belongs to the neighbor block: discard.
    B.x += (d0 == 0) ? v.x : 0.f;  C.x += (d0 > 0) ? v.x : 0.f;
    B.y += (d1 == 0) ? v.y : 0.f;  C.y += (d1 > 0) ? v.y : 0.f;
    B.z += (d2 == 0) ? v.z : 0.f;  C.z += (d2 > 0) ? v.z : 0.f;
    B.w += (d3 == 0) ? v.w : 0.f;  C.w += (d3 > 0) ? v.w : 0.f;

    // ---- branch-free interior: f = fs+1 .. fs+SEG-2 (30 iterations) ----
    const float* irow = ibase + (size_t)(fs + 1) * Tdim;
    float*       orow = obase + (size_t)fs * Tdim;
    #pragma unroll 3
    for (int i = 0; i < SEG - 2; ++i) {
        A = B; B = C; C = z;
        row_d(irow, lane, notlast, v, d0, d1, d2, d3);
        ACCUM3(A, B, C, v, d0, d1, d2, d3);
        *reinterpret_cast<float4*>(orow) = A;   // out[f-1] complete
        irow += Tdim;
        orow += Tdim;
    }

    // ---- last interior row f = fs+SEG-1 (holds the f==Fdim-1 clamp) ----
    A = B; B = C;
    row_d(irow, lane, notlast, v, d0, d1, d2, d3);
    if (fs + SEG == Fdim) {   // clip at upper F edge: up-moves stay
        d0 = min(d0, 0); d1 = min(d1, 0); d2 = min(d2, 0); d3 = min(d3, 0);
    }
    // C-part (d>0 -> out[fs+SEG]) belongs to the neighbor block: discard.
    A.x += (d0 < 0) ? v.x : 0.f;  B.x += (d0 == 0) ? v.x : 0.f;
    A.y += (d1 < 0) ? v.y : 0.f;  B.y += (d1 == 0) ? v.y : 0.f;
    A.z += (d2 < 0) ? v.z : 0.f;  B.z += (d2 == 0) ? v.z : 0.f;
    A.w += (d3 < 0) ? v.w : 0.f;  B.w += (d3 == 0) ? v.w : 0.f;
    *reinterpret_cast<float4*>(orow) = A;       // out[fs+SEG-2]
    orow += Tdim;

    // ---- upper ghost row f = fs+SEG: contributes only to out[fs+SEG-1] ----
    if (fs + SEG < Fdim) {   // block-uniform
        row_d(irow + Tdim, lane, notlast, v, d0, d1, d2, d3);
        B.x += (d0 < 0) ? v.x : 0.f;
        B.y += (d1 < 0) ? v.y : 0.f;
        B.z += (d2 < 0) ? v.z : 0.f;
        B.w += (d3 < 0) ? v.w : 0.f;
    }
    *reinterpret_cast<float4*>(orow) = B;       // out[fs+SEG-1] complete
}

extern "C" void kernel_launch(void* const* d_in, const int* in_sizes, int n_in,
                              void* d_out, int out_size) {
    const float* coeffs = (const float*)d_in[0];
    float* out = (float*)d_out;

    dim3 grid(Tdim / 4 / TPB, Bdim, NSEG);   // (16, 16, 8) = 2048 CTAs
    dim3 block(TPB);
    sst_gather_kernel<<<grid, block>>>(coeffs, out);
}